// round 4
// baseline (speedup 1.0000x reference)
#include <cuda_runtime.h>
#include <math.h>

// x: [B=2, T=64, C=16, H=128, W=128] f32; qkv conv 3x3 pad1 (16->16),
// nh=8, hc=2, D=32768; causal softmax T=64; out conv 3x3 (16->16).
#define HW 16384
typedef unsigned long long ull;

// ---------------- packed fp32x2 helpers (FFMA2 path, 2x fp32 tput) --------
__device__ __forceinline__ ull pk2(float lo, float hi) {
    ull r;
    asm("mov.b64 %0, {%1, %2};"
        : "=l"(r) : "r"(__float_as_uint(lo)), "r"(__float_as_uint(hi)));
    return r;
}
__device__ __forceinline__ void fma2(ull& d, ull a, ull b) {
    asm("fma.rn.f32x2 %0, %1, %2, %0;" : "+l"(d) : "l"(a), "l"(b));
}
__device__ __forceinline__ float2 upk(ull v) {
    unsigned lo, hi;
    asm("mov.b64 {%0, %1}, %2;" : "=r"(lo), "=r"(hi) : "l"(v));
    return make_float2(__uint_as_float(lo), __uint_as_float(hi));
}

// ---------------- scratch ----------------
__device__ float g_q[2*64*16*16384];   // q, later reused as attention output y
__device__ float g_k[2*64*16*16384];
__device__ float g_v[2*64*16*16384];
__device__ float g_part[64*16*64*64];  // QK^T partials per k-split
__device__ float g_att[16*64*64];      // softmax probs, [bh][s][t]

// ---------------- 3x3 conv, vertical-pair FFMA2 -------------------------
// Tile 64(w) x 8(h) per block, one conv per grid.z. Block 256 thr =
// 64 pixel-slots x 4 channel-groups. Thread = 4 w-cols x row-pair (h,h+4)
// x 4 output channels -> 16 packed accumulators.
// smem input layout: [c][g][w] of float2 = (row g-1, row g+3); every
// pixel operand is an aligned 8B load, no packing movs.
template<bool FINAL>
__global__ void __launch_bounds__(256, 2) conv3x3_kernel(
    const float* __restrict__ xin,
    const float* __restrict__ w0, const float* __restrict__ b0,
    const float* __restrict__ w1, const float* __restrict__ b1,
    const float* __restrict__ w2, const float* __restrict__ b2,
    float* __restrict__ out_final)
{
    extern __shared__ ull dyn[];
    ull* s_w2 = dyn;            // 16oc*16ic*10 packed (w,w) = 2560 ull
    ull* s_in = dyn + 2560;     // 16c * 6g * 68w float2-pairs = 6528 ull

    const int tid = threadIdx.x;
    const int bt  = blockIdx.y;                 // image 0..127
    const int cz  = blockIdx.z;                 // conv idx (qkv) / 0
    const int th0 = (blockIdx.x >> 1) * 8;
    const int tw0 = (blockIdx.x & 1) * 64;

    const float* x    = FINAL ? g_q : xin;
    const float* wsrc = FINAL ? w0 : (cz == 0 ? w0 : (cz == 1 ? w1 : w2));
    const float* bsrc = FINAL ? b0 : (cz == 0 ? b0 : (cz == 1 ? b1 : b2));
    float* outp       = FINAL ? out_final : (cz == 0 ? g_q : (cz == 1 ? g_k : g_v));

    // stage weights duplicated into both lanes: [(oc*16+ic)*10 + j]
    for (int idx = tid; idx < 2304; idx += 256) {
        int oc = idx / 144;
        int r  = idx - oc*144;
        int ic = r / 9;
        int j  = r - ic*9;
        unsigned bb = __float_as_uint(wsrc[idx]);
        s_w2[(oc*16 + ic)*10 + j] = ((ull)bb << 32) | bb;
    }

    // stage input halo tile into row-pair groups.
    // group g of channel c at word w holds (row th0+g-1, row th0+g+3), col tw0+w-1.
    {
        float* f = (float*)s_in;
        const int c = tid >> 4;
        const int l = tid & 15;
        const float* xc = x + ((size_t)bt*16 + c)*HW;
        for (int rr = 0; rr < 10; ++rr) {       // tile-relative row = rr-1
            int gh = th0 + rr - 1;
            bool rok = (gh >= 0) && (gh < 128);
            for (int wi = l; wi < 66; wi += 16) {
                int gw = tw0 + wi - 1;
                float v = 0.f;
                if (rok && gw >= 0 && gw < 128) v = xc[gh*128 + gw];
                int g1 = rr;        // lo lane of group rr (row rr-1)
                int g2 = rr - 4;    // hi lane of group rr-4 (row (rr-4)+3)
                if (g1 < 6)  f[(((c*6 + g1)*68 + wi) << 1)    ] = v;
                if (g2 >= 0) f[(((c*6 + g2)*68 + wi) << 1) + 1] = v;
            }
        }
    }
    __syncthreads();

    const int slot = tid & 63;
    const int cg   = tid >> 6;          // 4 oc each
    const int w0i  = (slot & 15) * 4;   // strip col start (tile-local)
    const int rp   = slot >> 4;         // row-pair 0..3 -> rows (rp, rp+4)

    ull acc[4][4];
#pragma unroll
    for (int c = 0; c < 4; ++c) {
        float bb = bsrc[cg*4 + c];
        ull b2 = pk2(bb, bb);
#pragma unroll
        for (int wt = 0; wt < 4; ++wt) acc[c][wt] = b2;
    }

    const ull* Sp = s_in + rp*68 + w0i;     // + ic*408 + ky*68 + j
    for (int ic = 0; ic < 16; ++ic) {
        const ull* p0 = Sp + ic*408;
        ull e[3][6];
#pragma unroll
        for (int ky = 0; ky < 3; ++ky)
#pragma unroll
            for (int j = 0; j < 6; ++j)
                e[ky][j] = p0[ky*68 + j];

#pragma unroll
        for (int c = 0; c < 4; ++c) {
            const ull* wp = s_w2 + ((cg*4 + c)*16 + ic)*10;
            ulonglong2 wA = *(const ulonglong2*)wp;        // taps 0,1
            ulonglong2 wB = *(const ulonglong2*)(wp + 2);  // taps 2,3
            ulonglong2 wC = *(const ulonglong2*)(wp + 4);  // taps 4,5
            ulonglong2 wD = *(const ulonglong2*)(wp + 6);  // taps 6,7
            ull w8 = wp[8];
#pragma unroll
            for (int wt = 0; wt < 4; ++wt) {
                ull a = acc[c][wt];
                fma2(a, e[0][wt+0], wA.x);
                fma2(a, e[0][wt+1], wA.y);
                fma2(a, e[0][wt+2], wB.x);
                fma2(a, e[1][wt+0], wB.y);
                fma2(a, e[1][wt+1], wC.x);
                fma2(a, e[1][wt+2], wC.y);
                fma2(a, e[2][wt+0], wD.x);
                fma2(a, e[2][wt+1], wD.y);
                fma2(a, e[2][wt+2], w8);
                acc[c][wt] = a;
            }
        }
    }

    const int ohl = th0 + rp;
    const int ohh = ohl + 4;
    const int ow  = tw0 + w0i;
#pragma unroll
    for (int c = 0; c < 4; ++c) {
        int oc = cg*4 + c;
        size_t base = ((size_t)bt*16 + oc)*HW;
        float2 v0 = upk(acc[c][0]);
        float2 v1 = upk(acc[c][1]);
        float2 v2 = upk(acc[c][2]);
        float2 v3 = upk(acc[c][3]);
        *(float4*)(outp + base + ohl*128 + ow) = make_float4(v0.x, v1.x, v2.x, v3.x);
        *(float4*)(outp + base + ohh*128 + ow) = make_float4(v0.y, v1.y, v2.y, v3.y);
    }
}

// ---------------- QK^T with K-split, FFMA2 inner ----------------
__global__ void __launch_bounds__(256) qk_kernel()
{
    __shared__ __align__(16) float Qs[64][68];
    __shared__ __align__(16) float Ks[64][68];
    const int bh = blockIdx.y;
    const int b  = bh >> 3, h = bh & 7;
    const int split = blockIdx.x;
    const int tid = threadIdx.x;
    const int ty = tid >> 4, tx = tid & 15;

    ull acc2[4][2];
#pragma unroll
    for (int i = 0; i < 4; ++i) { acc2[i][0] = 0ULL; acc2[i][1] = 0ULL; }

    for (int sub = 0; sub < 8; ++sub) {
        const int kc = split*512 + sub*64;
        __syncthreads();
        for (int i = tid; i < 1024; i += 256) {
            int t  = i >> 4;
            int kq = (i & 15) << 2;
            size_t base = ((size_t)((b*64 + t)*16 + h*2))*HW + kc + kq;
            float4 qa = *(const float4*)(g_q + base);
            float4 ka = *(const float4*)(g_k + base);
            Qs[kq+0][t] = qa.x; Qs[kq+1][t] = qa.y; Qs[kq+2][t] = qa.z; Qs[kq+3][t] = qa.w;
            Ks[kq+0][t] = ka.x; Ks[kq+1][t] = ka.y; Ks[kq+2][t] = ka.z; Ks[kq+3][t] = ka.w;
        }
        __syncthreads();
#pragma unroll 8
        for (int kk = 0; kk < 64; ++kk) {
            float4 a = *(const float4*)&Qs[kk][ty*4];
            ulonglong2 bp = *(const ulonglong2*)&Ks[kk][tx*4];
            ull a0 = pk2(a.x, a.x);
            ull a1 = pk2(a.y, a.y);
            ull a2 = pk2(a.z, a.z);
            ull a3 = pk2(a.w, a.w);
            fma2(acc2[0][0], a0, bp.x); fma2(acc2[0][1], a0, bp.y);
            fma2(acc2[1][0], a1, bp.x); fma2(acc2[1][1], a1, bp.y);
            fma2(acc2[2][0], a2, bp.x); fma2(acc2[2][1], a2, bp.y);
            fma2(acc2[3][0], a3, bp.x); fma2(acc2[3][1], a3, bp.y);
        }
    }

    float* dst = g_part + ((size_t)(split*16 + bh))*4096;
#pragma unroll
    for (int i = 0; i < 4; ++i) {
        float2 lo = upk(acc2[i][0]);
        float2 hi = upk(acc2[i][1]);
        *(float4*)(dst + (ty*4 + i)*64 + tx*4) = make_float4(lo.x, lo.y, hi.x, hi.y);
    }
}

// ---------------- split-reduce + causal softmax ----------------
__global__ void softmax_kernel()
{
    const int bh = blockIdx.y;
    const int t  = blockIdx.x;
    const int s  = threadIdx.x;

    float ssum = 0.f;
    for (int sp = 0; sp < 64; ++sp)
        ssum += g_part[((size_t)(sp*16 + bh)*64 + t)*64 + s];

    const float scale = rsqrtf(32768.0f);
    const bool valid = (s <= t);
    float logit = valid ? ssum * scale : -INFINITY;

    __shared__ float red[64];
    red[s] = logit;
    __syncthreads();
    for (int off = 32; off > 0; off >>= 1) {
        if (s < off) red[s] = fmaxf(red[s], red[s + off]);
        __syncthreads();
    }
    float mx = red[0];
    __syncthreads();
    float e = valid ? expf(logit - mx) : 0.f;
    red[s] = e;
    __syncthreads();
    for (int off = 32; off > 0; off >>= 1) {
        if (s < off) red[s] += red[s + off];
        __syncthreads();
    }
    float p = e / red[0];
    g_att[(bh*64 + s)*64 + t] = p;   // 0 for s > t
}

// ---------------- y = att @ V (packed over t, causal split) ----------------
__global__ void __launch_bounds__(256) av_kernel()
{
    __shared__ __align__(16) float sa[64][32];   // att[s][t0+tt]
    const int bh = blockIdx.z;
    const int b  = bh >> 3, h = bh & 7;
    const int thalf = blockIdx.y;
    const int t0 = thalf * 32;
    const int smax = thalf ? 64 : 32;   // causal: lower t-half only needs s<32
    const int d  = blockIdx.x*256 + threadIdx.x;

    for (int i = threadIdx.x; i < smax*8; i += 256) {
        int s = i >> 3; int tg = i & 7;
        *(float4*)&sa[s][tg*4] = *(const float4*)(g_att + (bh*64 + s)*64 + t0 + tg*4);
    }
    __syncthreads();

    ull acc2[16];
#pragma unroll
    for (int g = 0; g < 16; ++g) acc2[g] = 0ULL;

    const size_t vbase = ((size_t)(b*64*16 + h*2))*HW + d;
#pragma unroll 2
    for (int s = 0; s < smax; ++s) {
        float v = g_v[vbase + (size_t)s*16*HW];
        ull v2 = pk2(v, v);
#pragma unroll
        for (int g = 0; g < 8; ++g) {
            ulonglong2 ap = *(const ulonglong2*)&sa[s][g*4];
            fma2(acc2[g*2+0], ap.x, v2);
            fma2(acc2[g*2+1], ap.y, v2);
        }
    }

#pragma unroll
    for (int g = 0; g < 16; ++g) {
        float2 o = upk(acc2[g]);
        int t = t0 + g*2;
        g_q[((size_t)((b*64 + t  )*16 + h*2))*HW + d] = o.x;   // y aliases g_q
        g_q[((size_t)((b*64 + t+1)*16 + h*2))*HW + d] = o.y;
    }
}

// ---------------- launch ----------------
extern "C" void kernel_launch(void* const* d_in, const int* in_sizes, int n_in,
                              void* d_out, int out_size)
{
    const float* x  = (const float*)d_in[0];
    const float* wq = (const float*)d_in[1];
    const float* bq = (const float*)d_in[2];
    const float* wk = (const float*)d_in[3];
    const float* bk = (const float*)d_in[4];
    const float* wv = (const float*)d_in[5];
    const float* bv = (const float*)d_in[6];
    const float* wo = (const float*)d_in[7];
    const float* bo = (const float*)d_in[8];
    float* out = (float*)d_out;

    const int smem = (2560 + 6528) * 8;   // 72704 B
    cudaFuncSetAttribute(conv3x3_kernel<false>, cudaFuncAttributeMaxDynamicSharedMemorySize, smem);
    cudaFuncSetAttribute(conv3x3_kernel<true>,  cudaFuncAttributeMaxDynamicSharedMemorySize, smem);

    conv3x3_kernel<false><<<dim3(32, 128, 3), 256, smem>>>(x, wq, bq, wk, bk, wv, bv, nullptr);
    qk_kernel<<<dim3(64, 16), 256>>>();
    softmax_kernel<<<dim3(64, 16), 64>>>();
    av_kernel<<<dim3(128, 2, 16), 256>>>();
    conv3x3_kernel<true><<<dim3(32, 128, 1), 256, smem>>>(nullptr, wo, bo, nullptr, nullptr,
                                                          nullptr, nullptr, out);
}

// round 5
// speedup vs baseline: 1.5710x; 1.5710x over previous
#include <cuda_runtime.h>
#include <math.h>

// x: [B=2, T=64, C=16, H=128, W=128] f32; qkv conv 3x3 pad1 (16->16),
// nh=8, hc=2, D=32768; causal softmax T=64; out conv 3x3 (16->16).
#define HW 16384
typedef unsigned long long ull;

// ---------------- packed fp32x2 helpers (FFMA2 path, 2x fp32 tput) --------
__device__ __forceinline__ ull pk2(float lo, float hi) {
    ull r;
    asm("mov.b64 %0, {%1, %2};"
        : "=l"(r) : "r"(__float_as_uint(lo)), "r"(__float_as_uint(hi)));
    return r;
}
__device__ __forceinline__ void fma2(ull& d, ull a, ull b) {
    asm("fma.rn.f32x2 %0, %1, %2, %0;" : "+l"(d) : "l"(a), "l"(b));
}
__device__ __forceinline__ float2 upk(ull v) {
    unsigned lo, hi;
    asm("mov.b64 {%0, %1}, %2;" : "=r"(lo), "=r"(hi) : "l"(v));
    return make_float2(__uint_as_float(lo), __uint_as_float(hi));
}

// ---------------- scratch ----------------
__device__ float g_q[2*64*16*16384];   // q, later reused as attention output y
__device__ float g_k[2*64*16*16384];
__device__ float g_v[2*64*16*16384];
__device__ float g_part[64*16*64*64];  // QK^T partials per k-split
__device__ float g_att[16*64*64];      // softmax probs, [bh][s][t]

// ---------------- 3x3 conv, channel-pair FFMA2 ---------------------------
// f32x2 lanes = two OUTPUT CHANNELS (2q, 2q+1): exact same arithmetic per
// lane as scalar, half the FMA instructions. R1's proven tiling/memory
// pattern, 128-thread blocks (warp = channel-group), tile 32(w) x 4(h).
// Thread = 4 pixels x PPG channel-pairs.
template<int NCONV>
__global__ void __launch_bounds__(128) conv3x3_kernel(
    const float* __restrict__ xin,
    const float* __restrict__ w0, const float* __restrict__ b0,
    const float* __restrict__ w1, const float* __restrict__ b1,
    const float* __restrict__ w2, const float* __restrict__ b2,
    float* __restrict__ out_final)
{
    constexpr int NPAIR = NCONV * 8;     // channel pairs total
    constexpr int PPG   = NPAIR / 4;     // pairs per channel-group (warp)
    extern __shared__ ull dyn[];
    ull*   s_w2 = dyn;                          // NPAIR*16ic*10 packed (wA,wB)
    float* s_in = (float*)(dyn + NPAIR*160);    // 16c x 6row x 35 halo tile
    float* s_b  = s_in + 16*210;                // NCONV*16 biases

    const int tid = threadIdx.x;
    const int bt  = blockIdx.y;                 // image 0..127
    const int th0 = (blockIdx.x >> 2) * 4;      // tile origin h
    const int tw0 = (blockIdx.x & 3) * 32;      // tile origin w

    const float* x = (NCONV == 3) ? xin : g_q;  // final conv reads y (on g_q)

    // stage weights as channel-pair packs: [(pair*16+ic)*10 + j] = (w[2p], w[2p+1])
    {
        const float* wsrc[3] = {w0, w1, w2};
        for (int idx = tid; idx < NPAIR*144; idx += 128) {
            int pair = idx / 144;
            int r    = idx - pair*144;          // ic*9 + j
            int chA  = pair*2, chB = chA + 1;
            float a  = wsrc[chA >> 4][(chA & 15)*144 + r];
            float b  = wsrc[chB >> 4][(chB & 15)*144 + r];
            int ic   = r / 9;
            int j    = r - ic*9;
            s_w2[(pair*16 + ic)*10 + j] = pk2(a, b);
        }
        for (int idx = tid; idx < NCONV*16; idx += 128) {
            float bv;
            if (NCONV == 3) bv = (idx < 16) ? b0[idx] : (idx < 32 ? b1[idx-16] : b2[idx-32]);
            else            bv = b0[idx];
            s_b[idx] = bv;
        }
    }

    // stage input tile with halo: rows th0-1..th0+4, cols tw0-1..tw0+32
    for (int idx = tid; idx < 16*6*34; idx += 128) {
        int c   = idx / 204;
        int rem = idx - c*204;
        int yy  = rem / 34;
        int xx  = rem - yy*34;
        int gh  = th0 + yy - 1;
        int gw  = tw0 + xx - 1;
        float v = 0.f;
        if (gh >= 0 && gh < 128 && gw >= 0 && gw < 128)
            v = x[((size_t)bt*16 + c)*HW + gh*128 + gw];
        s_in[c*210 + yy*35 + xx] = v;
    }
    __syncthreads();

    const int cg  = tid >> 5;           // warp = channel group (PPG pairs)
    const int sl  = tid & 31;           // pixel slot
    const int py  = sl >> 3;            // tile row 0..3
    const int x0  = (sl & 7) * 4;       // tile col start

    ull acc[PPG][4];
#pragma unroll
    for (int c = 0; c < PPG; ++c) {
        int q = cg*PPG + c;
        ull b2 = pk2(s_b[2*q], s_b[2*q + 1]);
#pragma unroll
        for (int p = 0; p < 4; ++p) acc[c][p] = b2;
    }

    for (int ic = 0; ic < 16; ++ic) {
        const float* base = s_in + ic*210 + py*35 + x0;   // rows py..py+2
        ull pkk[3][6];
#pragma unroll
        for (int ky = 0; ky < 3; ++ky)
#pragma unroll
            for (int j = 0; j < 6; ++j) {
                float v = base[ky*35 + j];
                pkk[ky][j] = pk2(v, v);
            }
#pragma unroll
        for (int c = 0; c < PPG; ++c) {
            const ull* wp = s_w2 + ((cg*PPG + c)*16 + ic)*10;
            ulonglong2 wA = *(const ulonglong2*)wp;        // taps 0,1
            ulonglong2 wB = *(const ulonglong2*)(wp + 2);  // taps 2,3
            ulonglong2 wC = *(const ulonglong2*)(wp + 4);  // taps 4,5
            ulonglong2 wD = *(const ulonglong2*)(wp + 6);  // taps 6,7
            ull w8 = wp[8];
#pragma unroll
            for (int px = 0; px < 4; ++px) {
                ull a = acc[c][px];
                fma2(a, pkk[0][px+0], wA.x);
                fma2(a, pkk[0][px+1], wA.y);
                fma2(a, pkk[0][px+2], wB.x);
                fma2(a, pkk[1][px+0], wB.y);
                fma2(a, pkk[1][px+1], wC.x);
                fma2(a, pkk[1][px+2], wC.y);
                fma2(a, pkk[2][px+0], wD.x);
                fma2(a, pkk[2][px+1], wD.y);
                fma2(a, pkk[2][px+2], w8);
                acc[c][px] = a;
            }
        }
    }

    const int oh = th0 + py;
    const int ow = tw0 + x0;
#pragma unroll
    for (int c = 0; c < PPG; ++c) {
        int q    = cg*PPG + c;
        int chA  = 2*q, chB = chA + 1;
        float2 v0 = upk(acc[c][0]);
        float2 v1 = upk(acc[c][1]);
        float2 v2 = upk(acc[c][2]);
        float2 v3 = upk(acc[c][3]);
        float* outA;
        float* outB;
        if (NCONV == 3) {
            outA = (chA < 16) ? g_q : (chA < 32 ? g_k : g_v);
            outB = (chB < 16) ? g_q : (chB < 32 ? g_k : g_v);
        } else {
            outA = out_final; outB = out_final;
        }
        size_t offA = ((size_t)bt*16 + (chA & 15))*HW + oh*128 + ow;
        size_t offB = ((size_t)bt*16 + (chB & 15))*HW + oh*128 + ow;
        *(float4*)(outA + offA) = make_float4(v0.x, v1.x, v2.x, v3.x);
        *(float4*)(outB + offB) = make_float4(v0.y, v1.y, v2.y, v3.y);
    }
}

// ---------------- QK^T with K-split, FFMA2 inner ----------------
__global__ void __launch_bounds__(256) qk_kernel()
{
    __shared__ __align__(16) float Qs[64][68];
    __shared__ __align__(16) float Ks[64][68];
    const int bh = blockIdx.y;
    const int b  = bh >> 3, h = bh & 7;
    const int split = blockIdx.x;
    const int tid = threadIdx.x;
    const int ty = tid >> 4, tx = tid & 15;

    ull acc2[4][2];
#pragma unroll
    for (int i = 0; i < 4; ++i) { acc2[i][0] = 0ULL; acc2[i][1] = 0ULL; }

    for (int sub = 0; sub < 8; ++sub) {
        const int kc = split*512 + sub*64;
        __syncthreads();
        for (int i = tid; i < 1024; i += 256) {
            int t  = i >> 4;
            int kq = (i & 15) << 2;
            size_t base = ((size_t)((b*64 + t)*16 + h*2))*HW + kc + kq;
            float4 qa = *(const float4*)(g_q + base);
            float4 ka = *(const float4*)(g_k + base);
            Qs[kq+0][t] = qa.x; Qs[kq+1][t] = qa.y; Qs[kq+2][t] = qa.z; Qs[kq+3][t] = qa.w;
            Ks[kq+0][t] = ka.x; Ks[kq+1][t] = ka.y; Ks[kq+2][t] = ka.z; Ks[kq+3][t] = ka.w;
        }
        __syncthreads();
#pragma unroll 8
        for (int kk = 0; kk < 64; ++kk) {
            float4 a = *(const float4*)&Qs[kk][ty*4];
            ulonglong2 bp = *(const ulonglong2*)&Ks[kk][tx*4];
            ull a0 = pk2(a.x, a.x);
            ull a1 = pk2(a.y, a.y);
            ull a2 = pk2(a.z, a.z);
            ull a3 = pk2(a.w, a.w);
            fma2(acc2[0][0], a0, bp.x); fma2(acc2[0][1], a0, bp.y);
            fma2(acc2[1][0], a1, bp.x); fma2(acc2[1][1], a1, bp.y);
            fma2(acc2[2][0], a2, bp.x); fma2(acc2[2][1], a2, bp.y);
            fma2(acc2[3][0], a3, bp.x); fma2(acc2[3][1], a3, bp.y);
        }
    }

    float* dst = g_part + ((size_t)(split*16 + bh))*4096;
#pragma unroll
    for (int i = 0; i < 4; ++i) {
        float2 lo = upk(acc2[i][0]);
        float2 hi = upk(acc2[i][1]);
        *(float4*)(dst + (ty*4 + i)*64 + tx*4) = make_float4(lo.x, lo.y, hi.x, hi.y);
    }
}

// ---------------- split-reduce + causal softmax ----------------
__global__ void softmax_kernel()
{
    const int bh = blockIdx.y;
    const int t  = blockIdx.x;
    const int s  = threadIdx.x;

    float ssum = 0.f;
    for (int sp = 0; sp < 64; ++sp)
        ssum += g_part[((size_t)(sp*16 + bh)*64 + t)*64 + s];

    const float scale = rsqrtf(32768.0f);
    const bool valid = (s <= t);
    float logit = valid ? ssum * scale : -INFINITY;

    __shared__ float red[64];
    red[s] = logit;
    __syncthreads();
    for (int off = 32; off > 0; off >>= 1) {
        if (s < off) red[s] = fmaxf(red[s], red[s + off]);
        __syncthreads();
    }
    float mx = red[0];
    __syncthreads();
    float e = valid ? expf(logit - mx) : 0.f;
    red[s] = e;
    __syncthreads();
    for (int off = 32; off > 0; off >>= 1) {
        if (s < off) red[s] += red[s + off];
        __syncthreads();
    }
    float p = e / red[0];
    g_att[(bh*64 + s)*64 + t] = p;   // 0 for s > t
}

// ---------------- y = att @ V (packed over t, causal split) ----------------
__global__ void __launch_bounds__(256) av_kernel()
{
    __shared__ __align__(16) float sa[64][32];   // att[s][t0+tt]
    const int bh = blockIdx.z;
    const int b  = bh >> 3, h = bh & 7;
    const int thalf = blockIdx.y;
    const int t0 = thalf * 32;
    const int smax = thalf ? 64 : 32;   // causal: lower t-half only needs s<32
    const int d  = blockIdx.x*256 + threadIdx.x;

    for (int i = threadIdx.x; i < smax*8; i += 256) {
        int s = i >> 3; int tg = i & 7;
        *(float4*)&sa[s][tg*4] = *(const float4*)(g_att + (bh*64 + s)*64 + t0 + tg*4);
    }
    __syncthreads();

    ull acc2[16];
#pragma unroll
    for (int g = 0; g < 16; ++g) acc2[g] = 0ULL;

    const size_t vbase = ((size_t)(b*64*16 + h*2))*HW + d;
#pragma unroll 2
    for (int s = 0; s < smax; ++s) {
        float v = g_v[vbase + (size_t)s*16*HW];
        ull v2 = pk2(v, v);
#pragma unroll
        for (int g = 0; g < 8; ++g) {
            ulonglong2 ap = *(const ulonglong2*)&sa[s][g*4];
            fma2(acc2[g*2+0], ap.x, v2);
            fma2(acc2[g*2+1], ap.y, v2);
        }
    }

#pragma unroll
    for (int g = 0; g < 16; ++g) {
        float2 o = upk(acc2[g]);
        int t = t0 + g*2;
        g_q[((size_t)((b*64 + t  )*16 + h*2))*HW + d] = o.x;   // y aliases g_q
        g_q[((size_t)((b*64 + t+1)*16 + h*2))*HW + d] = o.y;
    }
}

// ---------------- launch ----------------
extern "C" void kernel_launch(void* const* d_in, const int* in_sizes, int n_in,
                              void* d_out, int out_size)
{
    const float* x  = (const float*)d_in[0];
    const float* wq = (const float*)d_in[1];
    const float* bq = (const float*)d_in[2];
    const float* wk = (const float*)d_in[3];
    const float* bk = (const float*)d_in[4];
    const float* wv = (const float*)d_in[5];
    const float* bv = (const float*)d_in[6];
    const float* wo = (const float*)d_in[7];
    const float* bo = (const float*)d_in[8];
    float* out = (float*)d_out;

    const int smem3 = 24*160*8 + 16*210*4 + 48*4;  // 44352 B
    const int smem1 = 8*160*8  + 16*210*4 + 16*4;  // 23744 B
    cudaFuncSetAttribute(conv3x3_kernel<3>, cudaFuncAttributeMaxDynamicSharedMemorySize, smem3);
    cudaFuncSetAttribute(conv3x3_kernel<1>, cudaFuncAttributeMaxDynamicSharedMemorySize, smem1);

    dim3 cgrid(128, 128);   // 128 tiles (32x4) x 128 images
    conv3x3_kernel<3><<<cgrid, 128, smem3>>>(x, wq, bq, wk, bk, wv, bv, nullptr);
    qk_kernel<<<dim3(64, 16), 256>>>();
    softmax_kernel<<<dim3(64, 16), 64>>>();
    av_kernel<<<dim3(128, 2, 16), 256>>>();
    conv3x3_kernel<1><<<cgrid, 128, smem1>>>(nullptr, wo, bo, nullptr, nullptr,
                                             nullptr, nullptr, out);
}